// round 1
// baseline (speedup 1.0000x reference)
#include <cuda_runtime.h>
#include <math.h>

#define N_NODES 16000
#define N_EDGES 256000
#define EPB 128            // threads (= edges) per block in edge kernel

#define R_CUT 2.5f
#define SQ3   1.7320508075688772f
#define PI_F  3.14159265358979323846f

// ---- scratch (device globals; no allocations allowed) ----
__device__ float g_attn[N_EDGES];
__device__ float g_ev[40 * N_EDGES];      // feature-major: [j][e]
__device__ float g_Z[N_NODES];
__device__ float g_qsw[N_NODES * 8];      // q_s folded with Ws_ss and 1/fan
__device__ float g_qvw[N_NODES * 12];     // q_v folded with Ws_vv and 1/(fan*SQ3)

// scales
#define INV_SQRT32 0.17677669529663687f   // 1/sqrt(32)
#define W2_SCALE   0.051031036307982884f  // (1/sqrt(16)) * (1/sqrt(24))  [W2 norm * TP inv]
#define INV_SQRT16 0.25f
#define INV_SQRT8  0.3535533905932738f
#define INV_FAN    0.11180339887498948f   // 1/sqrt(80)
#define RAD_COEF   5.059644256269407f     // sqrt(2/2.5)*sqrt(32)

// =====================================================================
// Kernel 1: per-node q (pre-contracted with Ws), zero Z and out
// =====================================================================
__global__ void node_prep_kernel(const float* __restrict__ x,
                                 const float* __restrict__ Wq_s,
                                 const float* __restrict__ Wq_v,
                                 const float* __restrict__ Ws_ss,
                                 const float* __restrict__ Ws_vv,
                                 float* __restrict__ out)
{
    int n = blockIdx.x * blockDim.x + threadIdx.x;
    if (n >= N_NODES) return;
    const float* xr = x + n * 40;

    float xs[16], xv[24];
    #pragma unroll
    for (int i = 0; i < 16; i++) xs[i] = xr[i];
    #pragma unroll
    for (int i = 0; i < 24; i++) xv[i] = xr[16 + i];

    float qs[8];
    #pragma unroll
    for (int o = 0; o < 8; o++) {
        float a = 0.f;
        #pragma unroll
        for (int i = 0; i < 16; i++) a = fmaf(xs[i], __ldg(&Wq_s[i * 8 + o]), a);
        qs[o] = a * INV_SQRT16;
    }
    float qv[12];
    #pragma unroll
    for (int o = 0; o < 4; o++)
        #pragma unroll
        for (int c = 0; c < 3; c++) {
            float a = 0.f;
            #pragma unroll
            for (int i = 0; i < 8; i++) a = fmaf(xv[i * 3 + c], __ldg(&Wq_v[i * 4 + o]), a);
            qv[o * 3 + c] = a * INV_SQRT8;
        }

    #pragma unroll
    for (int p = 0; p < 8; p++) {
        float a = 0.f;
        #pragma unroll
        for (int o = 0; o < 8; o++) a = fmaf(qs[o], __ldg(&Ws_ss[o * 8 + p]), a);
        g_qsw[n * 8 + p] = a * INV_FAN;
    }
    const float invfs = INV_FAN / SQ3;
    #pragma unroll
    for (int p = 0; p < 4; p++)
        #pragma unroll
        for (int c = 0; c < 3; c++) {
            float a = 0.f;
            #pragma unroll
            for (int o = 0; o < 4; o++) a = fmaf(qv[o * 3 + c], __ldg(&Ws_vv[o * 4 + p]), a);
            g_qvw[n * 12 + p * 3 + c] = a * invfs;
        }

    g_Z[n] = 0.f;
    #pragma unroll
    for (int j = 0; j < 40; j++) out[n * 40 + j] = 0.f;
}

// =====================================================================
// Kernel 2: per-edge: radial basis -> MLPs -> tensor product -> attn, v
// =====================================================================
// Dynamic smem layout (floats):
//  [0,512)        sWk1  (pre-scaled by 1/sqrt32), [n*16+t]
//  [512,1024)     sWv1
//  [1024,5632)    sWk2  transposed [j*16+t], scaled by W2_SCALE  (288 cols)
//  [5632,14848)   sWv2  transposed [j*16+t], scaled                (576 cols)
//  [14848,20992)  per-thread x stage: 48 feats x 128 threads  [feat*128+tid]
#define SM_WK1 0
#define SM_WV1 512
#define SM_WK2 1024
#define SM_WV2 5632
#define SM_X   14848
#define SM_FLOATS (14848 + 48 * EPB)

__global__ void __launch_bounds__(EPB)
edge_pass1_kernel(const float* __restrict__ pos, const float* __restrict__ x,
                  const float* __restrict__ Wk1, const float* __restrict__ Wk2,
                  const float* __restrict__ Wv1, const float* __restrict__ Wv2,
                  const int* __restrict__ esrc, const int* __restrict__ edst)
{
    extern __shared__ float smem[];
    float* sWk1 = smem + SM_WK1;
    float* sWv1 = smem + SM_WV1;
    float* sWk2 = smem + SM_WK2;
    float* sWv2 = smem + SM_WV2;
    float* sX   = smem + SM_X;
    const int tid = threadIdx.x;

    // ---- stage weights (scaled; W2 transposed to column-major) ----
    for (int idx = tid; idx < 512; idx += EPB) sWk1[idx] = Wk1[idx] * INV_SQRT32;
    for (int idx = tid; idx < 512; idx += EPB) sWv1[idx] = Wv1[idx] * INV_SQRT32;
    for (int idx = tid; idx < 288 * 16; idx += EPB) {
        int j = idx >> 4, t = idx & 15;
        sWk2[idx] = Wk2[t * 288 + j] * W2_SCALE;
    }
    for (int idx = tid; idx < 576 * 16; idx += EPB) {
        int j = idx >> 4, t = idx & 15;
        sWv2[idx] = Wv2[t * 576 + j] * W2_SCALE;
    }
    __syncthreads();

    const int e = blockIdx.x * EPB + tid;
    const int ns = esrc[e];
    const int nd = edst[e];

    float vx = pos[nd * 3 + 0] - pos[ns * 3 + 0];
    float vy = pos[nd * 3 + 1] - pos[ns * 3 + 1];
    float vz = pos[nd * 3 + 2] - pos[ns * 3 + 2];
    float d = sqrtf(vx * vx + vy * vy + vz * vz);

    float attn;
    if (d >= R_CUT) {
        // rad == 0 exactly -> h = silu(0) = 0 -> w = 0 -> k = v = 0 -> sim = 0
        attn = 1.0f;
        #pragma unroll
        for (int j = 0; j < 40; j++) g_ev[j * N_EDGES + e] = 0.f;
    } else {
        const float dsafe = fmaxf(d, 1e-6f);
        const float invd  = 1.0f / dsafe;
        const float vh0 = vx * invd, vh1 = vy * invd, vh2 = vz * invd;
        const float y10 = SQ3 * vh0, y11 = SQ3 * vh1, y12 = SQ3 * vh2;
        const float theta = (PI_F / R_CUT) * dsafe;
        const float coef  = RAD_COEF * invd;

        // ---- radial basis -> hidden pre-activations (both nets) ----
        float ak[16], av[16];
        #pragma unroll
        for (int t = 0; t < 16; t++) { ak[t] = 0.f; av[t] = 0.f; }
        #pragma unroll 1
        for (int n = 0; n < 32; n++) {
            float r = coef * sinf(theta * (float)(n + 1));
            const float* wkr = sWk1 + n * 16;
            const float* wvr = sWv1 + n * 16;
            #pragma unroll
            for (int t = 0; t < 16; t++) {
                ak[t] = fmaf(r, wkr[t], ak[t]);
                av[t] = fmaf(r, wvr[t], av[t]);
            }
        }
        float hk[16], hv[16];
        #pragma unroll
        for (int t = 0; t < 16; t++) {
            hk[t] = ak[t] / (1.f + expf(-ak[t]));   // silu
            hv[t] = av[t] / (1.f + expf(-av[t]));
        }

        // ---- stage source features in smem (runtime-indexable, conflict-free) ----
        const float* xr = x + ns * 40;
        #pragma unroll
        for (int i = 0; i < 40; i++) sX[i * EPB + tid] = xr[i];
        #pragma unroll
        for (int i = 0; i < 8; i++) {
            float u = sX[(16 + i * 3 + 0) * EPB + tid] * vh0
                    + sX[(16 + i * 3 + 1) * EPB + tid] * vh1
                    + sX[(16 + i * 3 + 2) * EPB + tid] * vh2;
            sX[(40 + i) * EPB + tid] = u;            // uv[i] = xv[i]·vh
        }
        #define XS(i) sX[(i) * EPB + tid]
        #define XVC(i) sX[(16 + (i)) * EPB + tid]
        #define UV(i) sX[(40 + (i)) * EPB + tid]

        // ================= K path (8 scalars, 4 vectors) =================
        float ks[8];  float kv[12];
        #pragma unroll
        for (int o = 0; o < 8; o++)  ks[o] = 0.f;
        #pragma unroll
        for (int o = 0; o < 12; o++) kv[o] = 0.f;

        // ss block: j = i*8+o, i<16
        #pragma unroll 1
        for (int i = 0; i < 16; i++) {
            float xi = XS(i);
            const float* cb = sWk2 + i * 8 * 16;
            #pragma unroll
            for (int o = 0; o < 8; o++) {
                float w = 0.f;
                #pragma unroll
                for (int t = 0; t < 16; t++) w = fmaf(hk[t], cb[o * 16 + t], w);
                ks[o] = fmaf(xi, w, ks[o]);
            }
        }
        // vv block: base 128, i<8  (uses uv = xv·vh, SQ3 folded out)
        #pragma unroll 1
        for (int i = 0; i < 8; i++) {
            float ui = UV(i);
            const float* cb = sWk2 + (128 + i * 8) * 16;
            #pragma unroll
            for (int o = 0; o < 8; o++) {
                float w = 0.f;
                #pragma unroll
                for (int t = 0; t < 16; t++) w = fmaf(hk[t], cb[o * 16 + t], w);
                ks[o] = fmaf(ui, w, ks[o]);
            }
        }
        // sv block: base 192, (16,4): kv[o][c] += xs[i]*w*y1[c]
        #pragma unroll 1
        for (int i = 0; i < 16; i++) {
            float xi = XS(i);
            const float* cb = sWk2 + (192 + i * 4) * 16;
            #pragma unroll
            for (int o = 0; o < 4; o++) {
                float w = 0.f;
                #pragma unroll
                for (int t = 0; t < 16; t++) w = fmaf(hk[t], cb[o * 16 + t], w);
                float xw = xi * w;
                kv[o * 3 + 0] = fmaf(xw, y10, kv[o * 3 + 0]);
                kv[o * 3 + 1] = fmaf(xw, y11, kv[o * 3 + 1]);
                kv[o * 3 + 2] = fmaf(xw, y12, kv[o * 3 + 2]);
            }
        }
        // vs block: base 256, (8,4): kv[o][c] += xv[i][c]*w
        #pragma unroll 1
        for (int i = 0; i < 8; i++) {
            const float* cb = sWk2 + (256 + i * 4) * 16;
            float x0 = XVC(i * 3 + 0), x1 = XVC(i * 3 + 1), x2 = XVC(i * 3 + 2);
            #pragma unroll
            for (int o = 0; o < 4; o++) {
                float w = 0.f;
                #pragma unroll
                for (int t = 0; t < 16; t++) w = fmaf(hk[t], cb[o * 16 + t], w);
                kv[o * 3 + 0] = fmaf(x0, w, kv[o * 3 + 0]);
                kv[o * 3 + 1] = fmaf(x1, w, kv[o * 3 + 1]);
                kv[o * 3 + 2] = fmaf(x2, w, kv[o * 3 + 2]);
            }
        }

        // sim & attn (q side pre-folded with Ws and scale factors)
        const float* qsw = g_qsw + nd * 8;
        const float* qvw = g_qvw + nd * 12;
        float sim = 0.f;
        #pragma unroll
        for (int p = 0; p < 8; p++)  sim = fmaf(qsw[p], ks[p], sim);
        #pragma unroll
        for (int p = 0; p < 12; p++) sim = fmaf(qvw[p], kv[p], sim);
        attn = expf(sim);

        // ================= V path (16 scalars, 8 vectors) =================
        float vs[16]; float vvv[24];
        #pragma unroll
        for (int o = 0; o < 16; o++) vs[o] = 0.f;
        #pragma unroll
        for (int o = 0; o < 24; o++) vvv[o] = 0.f;

        // ss: (16,16), base 0
        #pragma unroll 1
        for (int i = 0; i < 16; i++) {
            float xi = XS(i);
            const float* cb = sWv2 + i * 16 * 16;
            #pragma unroll
            for (int o = 0; o < 16; o++) {
                float w = 0.f;
                #pragma unroll
                for (int t = 0; t < 16; t++) w = fmaf(hv[t], cb[o * 16 + t], w);
                vs[o] = fmaf(xi, w, vs[o]);
            }
        }
        // vv: (8,16), base 256
        #pragma unroll 1
        for (int i = 0; i < 8; i++) {
            float ui = UV(i);
            const float* cb = sWv2 + (256 + i * 16) * 16;
            #pragma unroll
            for (int o = 0; o < 16; o++) {
                float w = 0.f;
                #pragma unroll
                for (int t = 0; t < 16; t++) w = fmaf(hv[t], cb[o * 16 + t], w);
                vs[o] = fmaf(ui, w, vs[o]);
            }
        }
        // sv: (16,8), base 384
        #pragma unroll 1
        for (int i = 0; i < 16; i++) {
            float xi = XS(i);
            const float* cb = sWv2 + (384 + i * 8) * 16;
            #pragma unroll
            for (int o = 0; o < 8; o++) {
                float w = 0.f;
                #pragma unroll
                for (int t = 0; t < 16; t++) w = fmaf(hv[t], cb[o * 16 + t], w);
                float xw = xi * w;
                vvv[o * 3 + 0] = fmaf(xw, y10, vvv[o * 3 + 0]);
                vvv[o * 3 + 1] = fmaf(xw, y11, vvv[o * 3 + 1]);
                vvv[o * 3 + 2] = fmaf(xw, y12, vvv[o * 3 + 2]);
            }
        }
        // vs: (8,8), base 512
        #pragma unroll 1
        for (int i = 0; i < 8; i++) {
            const float* cb = sWv2 + (512 + i * 8) * 16;
            float x0 = XVC(i * 3 + 0), x1 = XVC(i * 3 + 1), x2 = XVC(i * 3 + 2);
            #pragma unroll
            for (int o = 0; o < 8; o++) {
                float w = 0.f;
                #pragma unroll
                for (int t = 0; t < 16; t++) w = fmaf(hv[t], cb[o * 16 + t], w);
                vvv[o * 3 + 0] = fmaf(x0, w, vvv[o * 3 + 0]);
                vvv[o * 3 + 1] = fmaf(x1, w, vvv[o * 3 + 1]);
                vvv[o * 3 + 2] = fmaf(x2, w, vvv[o * 3 + 2]);
            }
        }

        #pragma unroll
        for (int j = 0; j < 16; j++) g_ev[j * N_EDGES + e] = vs[j];
        #pragma unroll
        for (int j = 0; j < 24; j++) g_ev[(16 + j) * N_EDGES + e] = vvv[j];
        #undef XS
        #undef XVC
        #undef UV
    }

    g_attn[e] = attn;
    atomicAdd(&g_Z[nd], attn);
}

// =====================================================================
// Kernel 3: attn -> attn / Z[dst]
// =====================================================================
__global__ void normalize_kernel(const int* __restrict__ edst)
{
    int e = blockIdx.x * blockDim.x + threadIdx.x;
    if (e >= N_EDGES) return;
    g_attn[e] = g_attn[e] / g_Z[edst[e]];
}

// =====================================================================
// Kernel 4: scatter a * v into out (fp32 RED atomics)
// =====================================================================
__global__ void scatter_kernel(const int* __restrict__ edst, float* __restrict__ out)
{
    int idx = blockIdx.x * blockDim.x + threadIdx.x;   // 40 * N_EDGES
    int j = idx / N_EDGES;
    int e = idx - j * N_EDGES;
    float val = g_attn[e] * g_ev[idx];
    if (val != 0.f) atomicAdd(&out[edst[e] * 40 + j], val);
}

// =====================================================================
extern "C" void kernel_launch(void* const* d_in, const int* in_sizes, int n_in,
                              void* d_out, int out_size)
{
    const float* pos   = (const float*)d_in[0];
    const float* x     = (const float*)d_in[1];
    const float* Wq_s  = (const float*)d_in[2];
    const float* Wq_v  = (const float*)d_in[3];
    const float* Wk1   = (const float*)d_in[4];
    const float* Wk2   = (const float*)d_in[5];
    const float* Wv1   = (const float*)d_in[6];
    const float* Wv2   = (const float*)d_in[7];
    const float* Ws_ss = (const float*)d_in[8];
    const float* Ws_vv = (const float*)d_in[9];
    const int*   esrc  = (const int*)d_in[10];
    const int*   edst  = (const int*)d_in[11];
    float* out = (float*)d_out;
    (void)in_sizes; (void)n_in; (void)out_size;

    const int smem_bytes = SM_FLOATS * (int)sizeof(float);   // 83968
    cudaFuncSetAttribute(edge_pass1_kernel,
                         cudaFuncAttributeMaxDynamicSharedMemorySize, smem_bytes);

    node_prep_kernel<<<(N_NODES + 127) / 128, 128>>>(x, Wq_s, Wq_v, Ws_ss, Ws_vv, out);
    edge_pass1_kernel<<<N_EDGES / EPB, EPB, smem_bytes>>>(pos, x, Wk1, Wk2, Wv1, Wv2, esrc, edst);
    normalize_kernel<<<N_EDGES / 256, 256>>>(edst);
    scatter_kernel<<<(40 * N_EDGES) / 256, 256>>>(edst, out);
}

// round 2
// speedup vs baseline: 1.0758x; 1.0758x over previous
#include <cuda_runtime.h>
#include <math.h>

#define N_NODES 16000
#define N_EDGES 256000
#define EPB 128            // threads (= edges) per block in edge kernel

#define R_CUT 2.5f
#define SQ3   1.7320508075688772f
#define PI_F  3.14159265358979323846f

// ---- scratch (device globals; no allocations allowed) ----
__device__ float g_attn[N_EDGES];
__device__ float g_ev[40 * N_EDGES];      // feature-major: [j][e]
__device__ float g_Z[N_NODES];
__device__ float g_qsw[N_NODES * 8];      // q_s folded with Ws_ss and 1/fan
__device__ float g_qvw[N_NODES * 12];     // q_v folded with Ws_vv and 1/(fan*SQ3)

// scales
#define INV_SQRT32 0.17677669529663687f   // 1/sqrt(32)
#define W2_SCALE   0.051031036307982884f  // (1/sqrt(16)) * (1/sqrt(24))
#define INV_SQRT16 0.25f
#define INV_SQRT8  0.3535533905932738f
#define INV_FAN    0.11180339887498948f   // 1/sqrt(80)
#define RAD_COEF   5.059644256269407f     // sqrt(2/2.5)*sqrt(32)

// ---- packed fp32x2 helpers (Blackwell FFMA2 via PTX) ----
typedef unsigned long long u64t;

__device__ __forceinline__ u64t pk2(float a, float b) {
    u64t r; asm("mov.b64 %0, {%1, %2};" : "=l"(r) : "f"(a), "f"(b)); return r;
}
__device__ __forceinline__ u64t pkdup(float a) {
    u64t r; asm("mov.b64 %0, {%1, %1};" : "=l"(r) : "f"(a)); return r;
}
__device__ __forceinline__ float2 up2(u64t v) {
    float2 r; asm("mov.b64 {%0, %1}, %2;" : "=f"(r.x), "=f"(r.y) : "l"(v)); return r;
}
__device__ __forceinline__ void fma2(u64t& d, u64t a, u64t b) {
    asm("fma.rn.f32x2 %0, %1, %2, %3;" : "=l"(d) : "l"(a), "l"(b), "l"(d));
}

// 16-step packed inner product: w_pair = sum_t h2[t] * cb[t]
__device__ __forceinline__ u64t dot16(const u64t* __restrict__ cb,
                                      const u64t* __restrict__ h2) {
    u64t w = 0ull;
    #pragma unroll
    for (int t = 0; t < 16; t++) fma2(w, h2[t], cb[t]);
    return w;
}

// =====================================================================
// Kernel 1: per-node q (pre-contracted with Ws), zero Z and out
// =====================================================================
__global__ void node_prep_kernel(const float* __restrict__ x,
                                 const float* __restrict__ Wq_s,
                                 const float* __restrict__ Wq_v,
                                 const float* __restrict__ Ws_ss,
                                 const float* __restrict__ Ws_vv,
                                 float* __restrict__ out)
{
    int n = blockIdx.x * blockDim.x + threadIdx.x;
    if (n >= N_NODES) return;
    const float* xr = x + n * 40;

    float xs[16], xv[24];
    #pragma unroll
    for (int i = 0; i < 16; i++) xs[i] = xr[i];
    #pragma unroll
    for (int i = 0; i < 24; i++) xv[i] = xr[16 + i];

    float qs[8];
    #pragma unroll
    for (int o = 0; o < 8; o++) {
        float a = 0.f;
        #pragma unroll
        for (int i = 0; i < 16; i++) a = fmaf(xs[i], __ldg(&Wq_s[i * 8 + o]), a);
        qs[o] = a * INV_SQRT16;
    }
    float qv[12];
    #pragma unroll
    for (int o = 0; o < 4; o++)
        #pragma unroll
        for (int c = 0; c < 3; c++) {
            float a = 0.f;
            #pragma unroll
            for (int i = 0; i < 8; i++) a = fmaf(xv[i * 3 + c], __ldg(&Wq_v[i * 4 + o]), a);
            qv[o * 3 + c] = a * INV_SQRT8;
        }

    #pragma unroll
    for (int p = 0; p < 8; p++) {
        float a = 0.f;
        #pragma unroll
        for (int o = 0; o < 8; o++) a = fmaf(qs[o], __ldg(&Ws_ss[o * 8 + p]), a);
        g_qsw[n * 8 + p] = a * INV_FAN;
    }
    const float invfs = INV_FAN / SQ3;
    #pragma unroll
    for (int p = 0; p < 4; p++)
        #pragma unroll
        for (int c = 0; c < 3; c++) {
            float a = 0.f;
            #pragma unroll
            for (int o = 0; o < 4; o++) a = fmaf(qv[o * 3 + c], __ldg(&Ws_vv[o * 4 + p]), a);
            g_qvw[n * 12 + p * 3 + c] = a * invfs;
        }

    g_Z[n] = 0.f;
    #pragma unroll
    for (int j = 0; j < 40; j++) out[n * 40 + j] = 0.f;
}

// =====================================================================
// Kernel 2: per-edge radial basis -> MLPs -> tensor product -> attn, v
// Packed-pair (fp32x2) formulation.
// Dynamic smem layout (floats):
//  [0,512)        sWk1   [n*16+t]  (pre-scaled by 1/sqrt32); read as u64 pairs
//  [512,1024)     sWv1
//  [1024,5632)    sWk2   pair-major: u64 index P*16+t = (W2[t][2P], W2[t][2P+1])
//  [5632,14848)   sWv2   same, 288 pairs
//  [14848,20992)  per-thread x stage: 48 feats x 128 threads  [feat*128+tid]
// =====================================================================
#define SM_WK1 0
#define SM_WV1 512
#define SM_WK2 1024
#define SM_WV2 5632
#define SM_X   14848
#define SM_FLOATS (14848 + 48 * EPB)

__global__ void __launch_bounds__(EPB)
edge_pass1_kernel(const float* __restrict__ pos, const float* __restrict__ x,
                  const float* __restrict__ Wk1, const float* __restrict__ Wk2,
                  const float* __restrict__ Wv1, const float* __restrict__ Wv2,
                  const int* __restrict__ esrc, const int* __restrict__ edst)
{
    extern __shared__ float smem[];
    float* sWk1f = smem + SM_WK1;
    float* sWv1f = smem + SM_WV1;
    float* sWk2f = smem + SM_WK2;
    float* sWv2f = smem + SM_WV2;
    float* sX    = smem + SM_X;
    const int tid = threadIdx.x;

    // ---- stage weights ----
    for (int idx = tid; idx < 512; idx += EPB) sWk1f[idx] = Wk1[idx] * INV_SQRT32;
    for (int idx = tid; idx < 512; idx += EPB) sWv1f[idx] = Wv1[idx] * INV_SQRT32;
    // pair-major: float slot idx -> P=idx/32, t=(idx%32)/2, half=idx&1
    for (int idx = tid; idx < 288 * 16; idx += EPB) {
        int P = idx >> 5, rem = idx & 31, t = rem >> 1, half = rem & 1;
        sWk2f[idx] = Wk2[t * 288 + 2 * P + half] * W2_SCALE;
    }
    for (int idx = tid; idx < 576 * 16; idx += EPB) {
        int P = idx >> 5, rem = idx & 31, t = rem >> 1, half = rem & 1;
        sWv2f[idx] = Wv2[t * 576 + 2 * P + half] * W2_SCALE;
    }
    __syncthreads();

    const u64t* sWk1 = (const u64t*)sWk1f;   // [n*8 + t2]
    const u64t* sWv1 = (const u64t*)sWv1f;
    const u64t* sWk2 = (const u64t*)sWk2f;   // [P*16 + t]
    const u64t* sWv2 = (const u64t*)sWv2f;

    const int e = blockIdx.x * EPB + tid;
    const int ns = esrc[e];
    const int nd = edst[e];

    float vx = pos[nd * 3 + 0] - pos[ns * 3 + 0];
    float vy = pos[nd * 3 + 1] - pos[ns * 3 + 1];
    float vz = pos[nd * 3 + 2] - pos[ns * 3 + 2];
    float d = sqrtf(vx * vx + vy * vy + vz * vz);

    float attn;
    if (d >= R_CUT) {
        // rad == 0 exactly -> h = silu(0) = 0 -> w = 0 -> k = v = 0 -> sim = 0
        attn = 1.0f;
        #pragma unroll
        for (int j = 0; j < 40; j++) g_ev[j * N_EDGES + e] = 0.f;
    } else {
        const float dsafe = fmaxf(d, 1e-6f);
        const float invd  = 1.0f / dsafe;
        const float vh0 = vx * invd, vh1 = vy * invd, vh2 = vz * invd;
        const float y10 = SQ3 * vh0, y11 = SQ3 * vh1, y12 = SQ3 * vh2;
        const float theta = (PI_F / R_CUT) * dsafe;
        const float coef  = RAD_COEF * invd;

        // ---- radial basis -> hidden pre-activations (both nets), packed ----
        u64t akp[8], avp[8];
        #pragma unroll
        for (int t2 = 0; t2 < 8; t2++) { akp[t2] = 0ull; avp[t2] = 0ull; }
        #pragma unroll 1
        for (int n = 0; n < 32; n++) {
            float r = coef * sinf(theta * (float)(n + 1));
            u64t r2 = pkdup(r);
            const u64t* wkr = sWk1 + n * 8;
            const u64t* wvr = sWv1 + n * 8;
            #pragma unroll
            for (int t2 = 0; t2 < 8; t2++) {
                fma2(akp[t2], r2, wkr[t2]);
                fma2(avp[t2], r2, wvr[t2]);
            }
        }
        // silu; hk2[t] = (h_t, h_t)
        u64t hk2[16];
        #pragma unroll
        for (int t2 = 0; t2 < 8; t2++) {
            float2 a = up2(akp[t2]);
            float h0 = a.x / (1.f + __expf(-a.x));
            float h1 = a.y / (1.f + __expf(-a.y));
            hk2[2 * t2]     = pkdup(h0);
            hk2[2 * t2 + 1] = pkdup(h1);
        }

        // ---- stage source features in smem (runtime-indexable) ----
        const float* xr = x + ns * 40;
        #pragma unroll
        for (int i = 0; i < 40; i++) sX[i * EPB + tid] = xr[i];
        #pragma unroll
        for (int i = 0; i < 8; i++) {
            float u = sX[(16 + i * 3 + 0) * EPB + tid] * vh0
                    + sX[(16 + i * 3 + 1) * EPB + tid] * vh1
                    + sX[(16 + i * 3 + 2) * EPB + tid] * vh2;
            sX[(40 + i) * EPB + tid] = u;            // uv[i] = xv[i]·vh
        }
        #define XS(i)  sX[(i) * EPB + tid]
        #define XVC(i) sX[(16 + (i)) * EPB + tid]
        #define UV(i)  sX[(40 + (i)) * EPB + tid]

        // ================= K path: ks[8] (4 pairs), kv[4][3] (3ch x 2 pairs) ====
        u64t ksp[4];  u64t kvp[3][2];
        #pragma unroll
        for (int p = 0; p < 4; p++) ksp[p] = 0ull;
        #pragma unroll
        for (int c = 0; c < 3; c++) { kvp[c][0] = 0ull; kvp[c][1] = 0ull; }

        // ss block: pairs P = i*4 + p, i<16
        #pragma unroll 1
        for (int i = 0; i < 16; i++) {
            u64t xi2 = pkdup(XS(i));
            const u64t* cb = sWk2 + i * 4 * 16;
            #pragma unroll
            for (int p = 0; p < 4; p++) {
                u64t w = dot16(cb + p * 16, hk2);
                fma2(ksp[p], xi2, w);
            }
        }
        // vv block: P = 64 + i*4 + p, i<8  (multiplier uv, SQ3 folded)
        #pragma unroll 1
        for (int i = 0; i < 8; i++) {
            u64t ui2 = pkdup(UV(i));
            const u64t* cb = sWk2 + (64 + i * 4) * 16;
            #pragma unroll
            for (int p = 0; p < 4; p++) {
                u64t w = dot16(cb + p * 16, hk2);
                fma2(ksp[p], ui2, w);
            }
        }
        // sv block: P = 96 + i*2 + p, i<16: kv[o][c] += xs_i * w_o * y1c
        #pragma unroll 1
        for (int i = 0; i < 16; i++) {
            float xi = XS(i);
            u64t xy0 = pkdup(xi * y10), xy1 = pkdup(xi * y11), xy2 = pkdup(xi * y12);
            const u64t* cb = sWk2 + (96 + i * 2) * 16;
            #pragma unroll
            for (int p = 0; p < 2; p++) {
                u64t w = dot16(cb + p * 16, hk2);
                fma2(kvp[0][p], xy0, w);
                fma2(kvp[1][p], xy1, w);
                fma2(kvp[2][p], xy2, w);
            }
        }
        // vs block: P = 128 + i*2 + p, i<8: kv[o][c] += xv[i][c] * w_o
        #pragma unroll 1
        for (int i = 0; i < 8; i++) {
            u64t x02 = pkdup(XVC(i * 3 + 0));
            u64t x12 = pkdup(XVC(i * 3 + 1));
            u64t x22 = pkdup(XVC(i * 3 + 2));
            const u64t* cb = sWk2 + (128 + i * 2) * 16;
            #pragma unroll
            for (int p = 0; p < 2; p++) {
                u64t w = dot16(cb + p * 16, hk2);
                fma2(kvp[0][p], x02, w);
                fma2(kvp[1][p], x12, w);
                fma2(kvp[2][p], x22, w);
            }
        }

        // sim & attn (q side pre-folded)
        const float* qsw = g_qsw + nd * 8;
        const float* qvw = g_qvw + nd * 12;
        float sim = 0.f;
        #pragma unroll
        for (int p = 0; p < 4; p++) {
            float2 k2 = up2(ksp[p]);
            sim = fmaf(qsw[2 * p], k2.x, sim);
            sim = fmaf(qsw[2 * p + 1], k2.y, sim);
        }
        #pragma unroll
        for (int p = 0; p < 2; p++)
            #pragma unroll
            for (int c = 0; c < 3; c++) {
                float2 k2 = up2(kvp[c][p]);
                sim = fmaf(qvw[(2 * p) * 3 + c], k2.x, sim);
                sim = fmaf(qvw[(2 * p + 1) * 3 + c], k2.y, sim);
            }
        attn = expf(sim);

        // ---- hv (from avp) now: frees K-path registers first ----
        u64t hv2[16];
        #pragma unroll
        for (int t2 = 0; t2 < 8; t2++) {
            float2 a = up2(avp[t2]);
            float h0 = a.x / (1.f + __expf(-a.x));
            float h1 = a.y / (1.f + __expf(-a.y));
            hv2[2 * t2]     = pkdup(h0);
            hv2[2 * t2 + 1] = pkdup(h1);
        }

        // ================= V path: vs[16] (8 pairs), vv[8][3] (3ch x 4 pairs) ====
        u64t vsp[8];  u64t vvp[3][4];
        #pragma unroll
        for (int p = 0; p < 8; p++) vsp[p] = 0ull;
        #pragma unroll
        for (int c = 0; c < 3; c++)
            #pragma unroll
            for (int p = 0; p < 4; p++) vvp[c][p] = 0ull;

        // ss: P = i*8 + p, i<16
        #pragma unroll 1
        for (int i = 0; i < 16; i++) {
            u64t xi2 = pkdup(XS(i));
            const u64t* cb = sWv2 + i * 8 * 16;
            #pragma unroll
            for (int p = 0; p < 8; p++) {
                u64t w = dot16(cb + p * 16, hv2);
                fma2(vsp[p], xi2, w);
            }
        }
        // vv: P = 128 + i*8 + p, i<8
        #pragma unroll 1
        for (int i = 0; i < 8; i++) {
            u64t ui2 = pkdup(UV(i));
            const u64t* cb = sWv2 + (128 + i * 8) * 16;
            #pragma unroll
            for (int p = 0; p < 8; p++) {
                u64t w = dot16(cb + p * 16, hv2);
                fma2(vsp[p], ui2, w);
            }
        }
        // sv: P = 192 + i*4 + p, i<16
        #pragma unroll 1
        for (int i = 0; i < 16; i++) {
            float xi = XS(i);
            u64t xy0 = pkdup(xi * y10), xy1 = pkdup(xi * y11), xy2 = pkdup(xi * y12);
            const u64t* cb = sWv2 + (192 + i * 4) * 16;
            #pragma unroll
            for (int p = 0; p < 4; p++) {
                u64t w = dot16(cb + p * 16, hv2);
                fma2(vvp[0][p], xy0, w);
                fma2(vvp[1][p], xy1, w);
                fma2(vvp[2][p], xy2, w);
            }
        }
        // vs: P = 256 + i*4 + p, i<8
        #pragma unroll 1
        for (int i = 0; i < 8; i++) {
            u64t x02 = pkdup(XVC(i * 3 + 0));
            u64t x12 = pkdup(XVC(i * 3 + 1));
            u64t x22 = pkdup(XVC(i * 3 + 2));
            const u64t* cb = sWv2 + (256 + i * 4) * 16;
            #pragma unroll
            for (int p = 0; p < 4; p++) {
                u64t w = dot16(cb + p * 16, hv2);
                fma2(vvp[0][p], x02, w);
                fma2(vvp[1][p], x12, w);
                fma2(vvp[2][p], x22, w);
            }
        }

        // stores (feature-major)
        #pragma unroll
        for (int p = 0; p < 8; p++) {
            float2 v2 = up2(vsp[p]);
            g_ev[(2 * p) * N_EDGES + e]     = v2.x;
            g_ev[(2 * p + 1) * N_EDGES + e] = v2.y;
        }
        #pragma unroll
        for (int p = 0; p < 4; p++)
            #pragma unroll
            for (int c = 0; c < 3; c++) {
                float2 v2 = up2(vvp[c][p]);
                g_ev[(16 + (2 * p) * 3 + c) * N_EDGES + e]     = v2.x;
                g_ev[(16 + (2 * p + 1) * 3 + c) * N_EDGES + e] = v2.y;
            }
        #undef XS
        #undef XVC
        #undef UV
    }

    g_attn[e] = attn;
    atomicAdd(&g_Z[nd], attn);
}

// =====================================================================
// Kernel 3: attn -> attn / Z[dst]
// =====================================================================
__global__ void normalize_kernel(const int* __restrict__ edst)
{
    int e = blockIdx.x * blockDim.x + threadIdx.x;
    if (e >= N_EDGES) return;
    g_attn[e] = g_attn[e] / g_Z[edst[e]];
}

// =====================================================================
// Kernel 4: scatter a * v into out (fp32 RED atomics)
// =====================================================================
__global__ void scatter_kernel(const int* __restrict__ edst, float* __restrict__ out)
{
    int idx = blockIdx.x * blockDim.x + threadIdx.x;   // 40 * N_EDGES
    int j = idx / N_EDGES;
    int e = idx - j * N_EDGES;
    float val = g_attn[e] * g_ev[idx];
    if (val != 0.f) atomicAdd(&out[edst[e] * 40 + j], val);
}

// =====================================================================
extern "C" void kernel_launch(void* const* d_in, const int* in_sizes, int n_in,
                              void* d_out, int out_size)
{
    const float* pos   = (const float*)d_in[0];
    const float* x     = (const float*)d_in[1];
    const float* Wq_s  = (const float*)d_in[2];
    const float* Wq_v  = (const float*)d_in[3];
    const float* Wk1   = (const float*)d_in[4];
    const float* Wk2   = (const float*)d_in[5];
    const float* Wv1   = (const float*)d_in[6];
    const float* Wv2   = (const float*)d_in[7];
    const float* Ws_ss = (const float*)d_in[8];
    const float* Ws_vv = (const float*)d_in[9];
    const int*   esrc  = (const int*)d_in[10];
    const int*   edst  = (const int*)d_in[11];
    float* out = (float*)d_out;
    (void)in_sizes; (void)n_in; (void)out_size;

    const int smem_bytes = SM_FLOATS * (int)sizeof(float);   // 83968
    cudaFuncSetAttribute(edge_pass1_kernel,
                         cudaFuncAttributeMaxDynamicSharedMemorySize, smem_bytes);

    node_prep_kernel<<<(N_NODES + 127) / 128, 128>>>(x, Wq_s, Wq_v, Ws_ss, Ws_vv, out);
    edge_pass1_kernel<<<N_EDGES / EPB, EPB, smem_bytes>>>(pos, x, Wk1, Wk2, Wv1, Wv2, esrc, edst);
    normalize_kernel<<<N_EDGES / 256, 256>>>(edst);
    scatter_kernel<<<(40 * N_EDGES) / 256, 256>>>(edst, out);
}

// round 3
// speedup vs baseline: 1.4554x; 1.3528x over previous
#include <cuda_runtime.h>
#include <math.h>

#define N_NODES 16000
#define N_EDGES 256000
#define EPB 128

#define R_CUT 2.5f
#define SQ3   1.7320508075688772f
#define PI_F  3.14159265358979323846f

// ---- scratch (device globals; no allocations allowed) ----
__device__ float g_attn[N_EDGES];
__device__ float g_hv[16 * N_EDGES];      // V-net hidden, [t][e]
__device__ float g_Z[N_NODES];
__device__ float g_qsw[N_NODES * 8];
__device__ float g_qvw[N_NODES * 12];

// scales
#define INV_SQRT32 0.17677669529663687f
#define W2_SCALE   0.051031036307982884f  // (1/sqrt16)*(1/sqrt24)
#define INV_SQRT16 0.25f
#define INV_SQRT8  0.3535533905932738f
#define INV_FAN    0.11180339887498948f   // 1/sqrt(80)
#define RAD_COEF   5.059644256269407f     // sqrt(2/2.5)*sqrt(32)

// ---- packed fp32x2 helpers ----
typedef unsigned long long u64t;

__device__ __forceinline__ u64t pkdup(float a) {
    u64t r; asm("mov.b64 %0, {%1, %1};" : "=l"(r) : "f"(a)); return r;
}
__device__ __forceinline__ float2 up2(u64t v) {
    float2 r; asm("mov.b64 {%0, %1}, %2;" : "=f"(r.x), "=f"(r.y) : "l"(v)); return r;
}
__device__ __forceinline__ void fma2(u64t& d, u64t a, u64t b) {
    asm("fma.rn.f32x2 %0, %1, %2, %3;" : "=l"(d) : "l"(a), "l"(b), "l"(d));
}

// quad dot: one LDS.128 per t feeds two packed FMAs (cols 4Q..4Q+3)
__device__ __forceinline__ void dotq(const ulonglong2* __restrict__ cb,
                                     const u64t* __restrict__ h2,
                                     u64t& w0, u64t& w1) {
    w0 = 0ull; w1 = 0ull;
    #pragma unroll
    for (int t = 0; t < 16; t++) {
        ulonglong2 q = cb[t];
        fma2(w0, h2[t], q.x);
        fma2(w1, h2[t], q.y);
    }
}

// =====================================================================
// Kernel 1: per-node q (pre-contracted with Ws), zero Z and out
// =====================================================================
__global__ void node_prep_kernel(const float* __restrict__ x,
                                 const float* __restrict__ Wq_s,
                                 const float* __restrict__ Wq_v,
                                 const float* __restrict__ Ws_ss,
                                 const float* __restrict__ Ws_vv,
                                 float* __restrict__ out)
{
    int n = blockIdx.x * blockDim.x + threadIdx.x;
    if (n >= N_NODES) return;
    const float* xr = x + n * 40;

    float xs[16], xv[24];
    #pragma unroll
    for (int i = 0; i < 16; i++) xs[i] = xr[i];
    #pragma unroll
    for (int i = 0; i < 24; i++) xv[i] = xr[16 + i];

    float qs[8];
    #pragma unroll
    for (int o = 0; o < 8; o++) {
        float a = 0.f;
        #pragma unroll
        for (int i = 0; i < 16; i++) a = fmaf(xs[i], __ldg(&Wq_s[i * 8 + o]), a);
        qs[o] = a * INV_SQRT16;
    }
    float qv[12];
    #pragma unroll
    for (int o = 0; o < 4; o++)
        #pragma unroll
        for (int c = 0; c < 3; c++) {
            float a = 0.f;
            #pragma unroll
            for (int i = 0; i < 8; i++) a = fmaf(xv[i * 3 + c], __ldg(&Wq_v[i * 4 + o]), a);
            qv[o * 3 + c] = a * INV_SQRT8;
        }

    #pragma unroll
    for (int p = 0; p < 8; p++) {
        float a = 0.f;
        #pragma unroll
        for (int o = 0; o < 8; o++) a = fmaf(qs[o], __ldg(&Ws_ss[o * 8 + p]), a);
        g_qsw[n * 8 + p] = a * INV_FAN;
    }
    const float invfs = INV_FAN / SQ3;
    #pragma unroll
    for (int p = 0; p < 4; p++)
        #pragma unroll
        for (int c = 0; c < 3; c++) {
            float a = 0.f;
            #pragma unroll
            for (int o = 0; o < 4; o++) a = fmaf(qv[o * 3 + c], __ldg(&Ws_vv[o * 4 + p]), a);
            g_qvw[n * 12 + p * 3 + c] = a * invfs;
        }

    g_Z[n] = 0.f;
    #pragma unroll
    for (int j = 0; j < 40; j++) out[n * 40 + j] = 0.f;
}

// =====================================================================
// Kernel 2 (K pass): basis -> hk,hv; store hv; K tensor product -> attn, Z
// smem (floats): [0,512) Wk1 rows, [512,1024) Wv1 rows,
//                [1024,5632) Wk2 quads [Q][t] float4 (72 quads)
// =====================================================================
#define KSM_FLOATS 5632

__global__ void __launch_bounds__(EPB)
edge_k_kernel(const float* __restrict__ pos, const float* __restrict__ x,
              const float* __restrict__ Wk1, const float* __restrict__ Wk2,
              const float* __restrict__ Wv1,
              const int* __restrict__ esrc, const int* __restrict__ edst)
{
    extern __shared__ float smem[];
    float* sWk1f = smem;
    float* sWv1f = smem + 512;
    float* sWk2f = smem + 1024;
    const int tid = threadIdx.x;

    for (int idx = tid; idx < 512; idx += EPB) sWk1f[idx] = Wk1[idx] * INV_SQRT32;
    for (int idx = tid; idx < 512; idx += EPB) sWv1f[idx] = Wv1[idx] * INV_SQRT32;
    // quad layout: float idx -> Q=idx/64, t=(idx>>2)&15, c=idx&3, col=4Q+c
    for (int idx = tid; idx < 72 * 64; idx += EPB) {
        int Q = idx >> 6, t = (idx >> 2) & 15, c = idx & 3;
        sWk2f[idx] = Wk2[t * 288 + 4 * Q + c] * W2_SCALE;
    }
    __syncthreads();

    const ulonglong2* sWk1q = (const ulonglong2*)sWk1f;   // [n*4 + q]
    const ulonglong2* sWv1q = (const ulonglong2*)sWv1f;
    const ulonglong2* sWk2q = (const ulonglong2*)sWk2f;   // [Q*16 + t]

    const int e = blockIdx.x * EPB + tid;
    const int ns = esrc[e];
    const int nd = edst[e];

    float vx = pos[nd * 3 + 0] - pos[ns * 3 + 0];
    float vy = pos[nd * 3 + 1] - pos[ns * 3 + 1];
    float vz = pos[nd * 3 + 2] - pos[ns * 3 + 2];
    float d = sqrtf(vx * vx + vy * vy + vz * vz);

    if (d >= R_CUT) {           // rad==0 -> k=v=0 -> sim=0 -> attn=1
        g_attn[e] = 1.0f;
        atomicAdd(&g_Z[nd], 1.0f);
        return;
    }

    const float dsafe = fmaxf(d, 1e-6f);
    const float invd  = 1.0f / dsafe;
    const float vh0 = vx * invd, vh1 = vy * invd, vh2 = vz * invd;
    const float y10 = SQ3 * vh0, y11 = SQ3 * vh1, y12 = SQ3 * vh2;
    const float theta = (PI_F / R_CUT) * dsafe;
    const float coef  = RAD_COEF * invd;

    // ---- radial basis -> both hidden pre-activations ----
    u64t akp[8], avp[8];
    #pragma unroll
    for (int t2 = 0; t2 < 8; t2++) { akp[t2] = 0ull; avp[t2] = 0ull; }
    #pragma unroll 1
    for (int n = 0; n < 32; n++) {
        float r = coef * sinf(theta * (float)(n + 1));
        u64t r2 = pkdup(r);
        const ulonglong2* wk = sWk1q + n * 4;
        const ulonglong2* wv = sWv1q + n * 4;
        #pragma unroll
        for (int q = 0; q < 4; q++) {
            ulonglong2 a = wk[q];
            fma2(akp[2 * q], r2, a.x);
            fma2(akp[2 * q + 1], r2, a.y);
            ulonglong2 b = wv[q];
            fma2(avp[2 * q], r2, b.x);
            fma2(avp[2 * q + 1], r2, b.y);
        }
    }
    // silu: hk kept packed; hv stored to global (frees regs)
    u64t hk2[16];
    #pragma unroll
    for (int t2 = 0; t2 < 8; t2++) {
        float2 a = up2(akp[t2]);
        hk2[2 * t2]     = pkdup(a.x / (1.f + __expf(-a.x)));
        hk2[2 * t2 + 1] = pkdup(a.y / (1.f + __expf(-a.y)));
        float2 b = up2(avp[t2]);
        g_hv[(2 * t2) * N_EDGES + e]     = b.x / (1.f + __expf(-b.x));
        g_hv[(2 * t2 + 1) * N_EDGES + e] = b.y / (1.f + __expf(-b.y));
    }

    // ---- source features in registers ----
    const float4* xr4 = (const float4*)(x + ns * 40);
    float xs[16];
    {
        float4 a = xr4[0], b = xr4[1], c = xr4[2], dd = xr4[3];
        xs[0]=a.x; xs[1]=a.y; xs[2]=a.z; xs[3]=a.w;
        xs[4]=b.x; xs[5]=b.y; xs[6]=b.z; xs[7]=b.w;
        xs[8]=c.x; xs[9]=c.y; xs[10]=c.z; xs[11]=c.w;
        xs[12]=dd.x; xs[13]=dd.y; xs[14]=dd.z; xs[15]=dd.w;
    }

    u64t ksp[4];  u64t kvp[3][2];
    #pragma unroll
    for (int p = 0; p < 4; p++) ksp[p] = 0ull;
    #pragma unroll
    for (int c = 0; c < 3; c++) { kvp[c][0] = 0ull; kvp[c][1] = 0ull; }

    // ss block: quads 2i, 2i+1 -> ksp[0..3]
    #pragma unroll
    for (int i = 0; i < 16; i++) {
        u64t xi2 = pkdup(xs[i]);
        u64t w0, w1;
        dotq(sWk2q + (2 * i) * 16, hk2, w0, w1);
        fma2(ksp[0], xi2, w0); fma2(ksp[1], xi2, w1);
        dotq(sWk2q + (2 * i + 1) * 16, hk2, w0, w1);
        fma2(ksp[2], xi2, w0); fma2(ksp[3], xi2, w1);
    }
    // sv block: quads 48+i: kv[o][c] += xs_i * w_o * y1c
    #pragma unroll
    for (int i = 0; i < 16; i++) {
        u64t xy0 = pkdup(xs[i] * y10), xy1 = pkdup(xs[i] * y11), xy2 = pkdup(xs[i] * y12);
        u64t w0, w1;
        dotq(sWk2q + (48 + i) * 16, hk2, w0, w1);
        fma2(kvp[0][0], xy0, w0); fma2(kvp[0][1], xy0, w1);
        fma2(kvp[1][0], xy1, w0); fma2(kvp[1][1], xy1, w1);
        fma2(kvp[2][0], xy2, w0); fma2(kvp[2][1], xy2, w1);
    }
    // vector features
    float xv[24];
    {
        float4 a = xr4[4], b = xr4[5], c = xr4[6], dd = xr4[7], ee = xr4[8], ff = xr4[9];
        xv[0]=a.x; xv[1]=a.y; xv[2]=a.z; xv[3]=a.w;
        xv[4]=b.x; xv[5]=b.y; xv[6]=b.z; xv[7]=b.w;
        xv[8]=c.x; xv[9]=c.y; xv[10]=c.z; xv[11]=c.w;
        xv[12]=dd.x; xv[13]=dd.y; xv[14]=dd.z; xv[15]=dd.w;
        xv[16]=ee.x; xv[17]=ee.y; xv[18]=ee.z; xv[19]=ee.w;
        xv[20]=ff.x; xv[21]=ff.y; xv[22]=ff.z; xv[23]=ff.w;
    }
    float uv[8];
    #pragma unroll
    for (int i = 0; i < 8; i++)
        uv[i] = xv[i*3+0]*vh0 + xv[i*3+1]*vh1 + xv[i*3+2]*vh2;

    // vv block: quads 32+2i, 33+2i (multiplier uv)
    #pragma unroll
    for (int i = 0; i < 8; i++) {
        u64t ui2 = pkdup(uv[i]);
        u64t w0, w1;
        dotq(sWk2q + (32 + 2 * i) * 16, hk2, w0, w1);
        fma2(ksp[0], ui2, w0); fma2(ksp[1], ui2, w1);
        dotq(sWk2q + (33 + 2 * i) * 16, hk2, w0, w1);
        fma2(ksp[2], ui2, w0); fma2(ksp[3], ui2, w1);
    }
    // vs block: quads 64+i: kv[o][c] += xv[i][c] * w_o
    #pragma unroll
    for (int i = 0; i < 8; i++) {
        u64t x02 = pkdup(xv[i*3+0]), x12 = pkdup(xv[i*3+1]), x22 = pkdup(xv[i*3+2]);
        u64t w0, w1;
        dotq(sWk2q + (64 + i) * 16, hk2, w0, w1);
        fma2(kvp[0][0], x02, w0); fma2(kvp[0][1], x02, w1);
        fma2(kvp[1][0], x12, w0); fma2(kvp[1][1], x12, w1);
        fma2(kvp[2][0], x22, w0); fma2(kvp[2][1], x22, w1);
    }

    // sim & attn
    const float* qsw = g_qsw + nd * 8;
    const float* qvw = g_qvw + nd * 12;
    float sim = 0.f;
    #pragma unroll
    for (int p = 0; p < 4; p++) {
        float2 k2 = up2(ksp[p]);
        sim = fmaf(qsw[2 * p], k2.x, sim);
        sim = fmaf(qsw[2 * p + 1], k2.y, sim);
    }
    #pragma unroll
    for (int p = 0; p < 2; p++)
        #pragma unroll
        for (int c = 0; c < 3; c++) {
            float2 k2 = up2(kvp[c][p]);
            sim = fmaf(qvw[(2 * p) * 3 + c], k2.x, sim);
            sim = fmaf(qvw[(2 * p + 1) * 3 + c], k2.y, sim);
        }
    float attn = expf(sim);
    g_attn[e] = attn;
    atomicAdd(&g_Z[nd], attn);
}

// =====================================================================
// Kernel 3 (V pass): hv from scratch; V tensor product; scatter a*v
// smem: Wv2 quads [Q][t] float4, 144 quads -> 9216 floats
// =====================================================================
#define VSM_FLOATS 9216

__global__ void __launch_bounds__(EPB)
edge_v_kernel(const float* __restrict__ pos, const float* __restrict__ x,
              const float* __restrict__ Wv2,
              const int* __restrict__ esrc, const int* __restrict__ edst,
              float* __restrict__ out)
{
    extern __shared__ float smem[];
    float* sWv2f = smem;
    const int tid = threadIdx.x;

    for (int idx = tid; idx < 144 * 64; idx += EPB) {
        int Q = idx >> 6, t = (idx >> 2) & 15, c = idx & 3;
        sWv2f[idx] = Wv2[t * 576 + 4 * Q + c] * W2_SCALE;
    }
    __syncthreads();
    const ulonglong2* sWv2q = (const ulonglong2*)sWv2f;

    const int e = blockIdx.x * EPB + tid;
    const int ns = esrc[e];
    const int nd = edst[e];

    float vx = pos[nd * 3 + 0] - pos[ns * 3 + 0];
    float vy = pos[nd * 3 + 1] - pos[ns * 3 + 1];
    float vz = pos[nd * 3 + 2] - pos[ns * 3 + 2];
    float d = sqrtf(vx * vx + vy * vy + vz * vz);
    if (d >= R_CUT) return;     // v == 0 exactly

    const float dsafe = fmaxf(d, 1e-6f);
    const float invd  = 1.0f / dsafe;
    const float vh0 = vx * invd, vh1 = vy * invd, vh2 = vz * invd;
    const float y10 = SQ3 * vh0, y11 = SQ3 * vh1, y12 = SQ3 * vh2;

    const float a_norm = g_attn[e] / g_Z[nd];

    // hidden (precomputed by K pass)
    u64t hv2[16];
    #pragma unroll
    for (int t = 0; t < 16; t++) hv2[t] = pkdup(g_hv[t * N_EDGES + e]);

    const float4* xr4 = (const float4*)(x + ns * 40);
    float xs[16];
    {
        float4 a = xr4[0], b = xr4[1], c = xr4[2], dd = xr4[3];
        xs[0]=a.x; xs[1]=a.y; xs[2]=a.z; xs[3]=a.w;
        xs[4]=b.x; xs[5]=b.y; xs[6]=b.z; xs[7]=b.w;
        xs[8]=c.x; xs[9]=c.y; xs[10]=c.z; xs[11]=c.w;
        xs[12]=dd.x; xs[13]=dd.y; xs[14]=dd.z; xs[15]=dd.w;
    }

    u64t vsp[8];  u64t vvp[3][4];
    #pragma unroll
    for (int p = 0; p < 8; p++) vsp[p] = 0ull;
    #pragma unroll
    for (int c = 0; c < 3; c++)
        #pragma unroll
        for (int p = 0; p < 4; p++) vvp[c][p] = 0ull;

    // ss: quads 4i..4i+3 -> vsp[0..7]
    #pragma unroll
    for (int i = 0; i < 16; i++) {
        u64t xi2 = pkdup(xs[i]);
        #pragma unroll
        for (int qq = 0; qq < 4; qq++) {
            u64t w0, w1;
            dotq(sWv2q + (4 * i + qq) * 16, hv2, w0, w1);
            fma2(vsp[2 * qq], xi2, w0); fma2(vsp[2 * qq + 1], xi2, w1);
        }
    }
    // sv: quads 96+2i, 97+2i: vv[o][c] += xs_i * w_o * y1c
    #pragma unroll
    for (int i = 0; i < 16; i++) {
        u64t xy0 = pkdup(xs[i] * y10), xy1 = pkdup(xs[i] * y11), xy2 = pkdup(xs[i] * y12);
        #pragma unroll
        for (int qq = 0; qq < 2; qq++) {
            u64t w0, w1;
            dotq(sWv2q + (96 + 2 * i + qq) * 16, hv2, w0, w1);
            fma2(vvp[0][2 * qq], xy0, w0); fma2(vvp[0][2 * qq + 1], xy0, w1);
            fma2(vvp[1][2 * qq], xy1, w0); fma2(vvp[1][2 * qq + 1], xy1, w1);
            fma2(vvp[2][2 * qq], xy2, w0); fma2(vvp[2][2 * qq + 1], xy2, w1);
        }
    }

    float xv[24];
    {
        float4 a = xr4[4], b = xr4[5], c = xr4[6], dd = xr4[7], ee = xr4[8], ff = xr4[9];
        xv[0]=a.x; xv[1]=a.y; xv[2]=a.z; xv[3]=a.w;
        xv[4]=b.x; xv[5]=b.y; xv[6]=b.z; xv[7]=b.w;
        xv[8]=c.x; xv[9]=c.y; xv[10]=c.z; xv[11]=c.w;
        xv[12]=dd.x; xv[13]=dd.y; xv[14]=dd.z; xv[15]=dd.w;
        xv[16]=ee.x; xv[17]=ee.y; xv[18]=ee.z; xv[19]=ee.w;
        xv[20]=ff.x; xv[21]=ff.y; xv[22]=ff.z; xv[23]=ff.w;
    }
    float uv[8];
    #pragma unroll
    for (int i = 0; i < 8; i++)
        uv[i] = xv[i*3+0]*vh0 + xv[i*3+1]*vh1 + xv[i*3+2]*vh2;

    // vv: quads 64+4i..+3 (multiplier uv)
    #pragma unroll
    for (int i = 0; i < 8; i++) {
        u64t ui2 = pkdup(uv[i]);
        #pragma unroll
        for (int qq = 0; qq < 4; qq++) {
            u64t w0, w1;
            dotq(sWv2q + (64 + 4 * i + qq) * 16, hv2, w0, w1);
            fma2(vsp[2 * qq], ui2, w0); fma2(vsp[2 * qq + 1], ui2, w1);
        }
    }
    // vs: quads 128+2i, 129+2i: vv[o][c] += xv[i][c] * w_o
    #pragma unroll
    for (int i = 0; i < 8; i++) {
        u64t x02 = pkdup(xv[i*3+0]), x12 = pkdup(xv[i*3+1]), x22 = pkdup(xv[i*3+2]);
        #pragma unroll
        for (int qq = 0; qq < 2; qq++) {
            u64t w0, w1;
            dotq(sWv2q + (128 + 2 * i + qq) * 16, hv2, w0, w1);
            fma2(vvp[0][2 * qq], x02, w0); fma2(vvp[0][2 * qq + 1], x02, w1);
            fma2(vvp[1][2 * qq], x12, w0); fma2(vvp[1][2 * qq + 1], x12, w1);
            fma2(vvp[2][2 * qq], x22, w0); fma2(vvp[2][2 * qq + 1], x22, w1);
        }
    }

    // scatter a * v
    float* orow = out + nd * 40;
    #pragma unroll
    for (int p = 0; p < 8; p++) {
        float2 v2 = up2(vsp[p]);
        atomicAdd(&orow[2 * p],     a_norm * v2.x);
        atomicAdd(&orow[2 * p + 1], a_norm * v2.y);
    }
    #pragma unroll
    for (int p = 0; p < 4; p++)
        #pragma unroll
        for (int c = 0; c < 3; c++) {
            float2 v2 = up2(vvp[c][p]);
            atomicAdd(&orow[16 + (2 * p) * 3 + c],     a_norm * v2.x);
            atomicAdd(&orow[16 + (2 * p + 1) * 3 + c], a_norm * v2.y);
        }
}

// =====================================================================
extern "C" void kernel_launch(void* const* d_in, const int* in_sizes, int n_in,
                              void* d_out, int out_size)
{
    const float* pos   = (const float*)d_in[0];
    const float* x     = (const float*)d_in[1];
    const float* Wq_s  = (const float*)d_in[2];
    const float* Wq_v  = (const float*)d_in[3];
    const float* Wk1   = (const float*)d_in[4];
    const float* Wk2   = (const float*)d_in[5];
    const float* Wv1   = (const float*)d_in[6];
    const float* Wv2   = (const float*)d_in[7];
    const int*   esrc  = (const int*)d_in[10];
    const int*   edst  = (const int*)d_in[11];
    const float* Ws_ss = (const float*)d_in[8];
    const float* Ws_vv = (const float*)d_in[9];
    float* out = (float*)d_out;
    (void)in_sizes; (void)n_in; (void)out_size;

    const int ksm = KSM_FLOATS * (int)sizeof(float);   // 22528
    const int vsm = VSM_FLOATS * (int)sizeof(float);   // 36864
    cudaFuncSetAttribute(edge_k_kernel, cudaFuncAttributeMaxDynamicSharedMemorySize, ksm);
    cudaFuncSetAttribute(edge_v_kernel, cudaFuncAttributeMaxDynamicSharedMemorySize, vsm);

    node_prep_kernel<<<(N_NODES + 127) / 128, 128>>>(x, Wq_s, Wq_v, Ws_ss, Ws_vv, out);
    edge_k_kernel<<<N_EDGES / EPB, EPB, ksm>>>(pos, x, Wk1, Wk2, Wv1, esrc, edst);
    edge_v_kernel<<<N_EDGES / EPB, EPB, vsm>>>(pos, x, Wv2, esrc, edst, out);
}